// round 1
// baseline (speedup 1.0000x reference)
#include <cuda_runtime.h>
#include <cstdint>
#include <cstddef>

// ---------------- problem constants ----------------
#define BT   8
#define SEQL 4096
#define DM   128
#define DI   256
#define DS   16
#define DRK  8
#define MTOT (BT*SEQL)          // 32768 rows
#define NCH  16                 // scan chunks
#define LC   (SEQL/NCH)         // 256 steps per chunk
#define DPB  64                 // d-channels per scan block

// ---------------- scratch (device globals; no allocs) ----------------
__device__ float g_xz  [(size_t)MTOT*512];  // in_proj output: x raw [0:256), z [256:512)
__device__ float g_x   [(size_t)MTOT*DI];   // conv+silu output (u)
__device__ float g_xdbl[(size_t)MTOT*40];   // x_proj output: dt8[0:8) B[8:24) C[24:40)
__device__ float g_dtf [(size_t)MTOT*DI];   // softplus(dt_proj)
__device__ float g_y   [(size_t)MTOT*DI];   // scan output, fused gate
__device__ float g_h   [(size_t)MTOT*DM];   // out_proj output
__device__ float g_hn  [(size_t)MTOT*DM];   // layernorm output
__device__ float g_hend [NCH*BT*DI*DS];
__device__ float g_hinit[NCH*BT*DI*DS];
__device__ float g_tsum [NCH*BT*DI];

// ---------------- generic fp32 GEMM: C[M,N] = A[M,K] * B[N,K]^T ----------------
// A row-major [M,K], B row-major [N,K] (weight layout). ACT: 0=none, 1=relu.
template<int BM,int BN,int BK,int TM,int TN,int ACT>
__global__ void __launch_bounds__((BM/TM)*(BN/TN))
sgemm_nt(const float* __restrict__ A, const float* __restrict__ B,
         float* __restrict__ C, int M, int N, int K)
{
    constexpr int TH = (BM/TM)*(BN/TN);
    constexpr int KV = BK/4;
    __shared__ float As[BK][BM+4];
    __shared__ float Bs[BK][BN+4];

    const int tid = threadIdx.x;
    const int tx  = tid % (BN/TN);
    const int ty  = tid / (BN/TN);
    const int m0  = blockIdx.y * BM;
    const int n0  = blockIdx.x * BN;

    float acc[TM][TN];
    #pragma unroll
    for (int i=0;i<TM;i++)
        #pragma unroll
        for (int j=0;j<TN;j++) acc[i][j] = 0.f;

    for (int k0=0;k0<K;k0+=BK){
        // load A tile (M divisible by BM for all our calls)
        #pragma unroll
        for (int it=0; it<(BM*KV)/TH; ++it){
            int idx = tid + it*TH;
            int i = idx / KV, kq = idx % KV;
            const float4 v = *reinterpret_cast<const float4*>(
                &A[(size_t)(m0+i)*K + k0 + 4*kq]);
            As[4*kq+0][i]=v.x; As[4*kq+1][i]=v.y;
            As[4*kq+2][i]=v.z; As[4*kq+3][i]=v.w;
        }
        // load B tile (guard rows >= N: zero pad)
        #pragma unroll
        for (int it=0; it<(BN*KV)/TH; ++it){
            int idx = tid + it*TH;
            int i = idx / KV, kq = idx % KV;
            float4 v = make_float4(0.f,0.f,0.f,0.f);
            if (n0+i < N)
                v = *reinterpret_cast<const float4*>(
                    &B[(size_t)(n0+i)*K + k0 + 4*kq]);
            Bs[4*kq+0][i]=v.x; Bs[4*kq+1][i]=v.y;
            Bs[4*kq+2][i]=v.z; Bs[4*kq+3][i]=v.w;
        }
        __syncthreads();

        #pragma unroll
        for (int kk=0;kk<BK;kk++){
            float rm[TM], rn[TN];
            #pragma unroll
            for (int i=0;i<TM;i+=4){
                float4 v = *reinterpret_cast<const float4*>(&As[kk][ty*TM+i]);
                rm[i]=v.x; rm[i+1]=v.y; rm[i+2]=v.z; rm[i+3]=v.w;
            }
            #pragma unroll
            for (int j=0;j<TN;j+=4){
                float4 v = *reinterpret_cast<const float4*>(&Bs[kk][tx*TN+j]);
                rn[j]=v.x; rn[j+1]=v.y; rn[j+2]=v.z; rn[j+3]=v.w;
            }
            #pragma unroll
            for (int i=0;i<TM;i++)
                #pragma unroll
                for (int j=0;j<TN;j++)
                    acc[i][j] = fmaf(rm[i], rn[j], acc[i][j]);
        }
        __syncthreads();
    }

    #pragma unroll
    for (int i=0;i<TM;i++){
        int m = m0 + ty*TM + i;
        #pragma unroll
        for (int j=0;j<TN;j++){
            int n = n0 + tx*TN + j;
            if (n < N){
                float v = acc[i][j];
                if (ACT==1) v = fmaxf(v, 0.f);
                C[(size_t)m*N + n] = v;
            }
        }
    }
}

// ---------------- depthwise causal conv (k=4) + bias + silu ----------------
__global__ void conv_silu_kernel(const float* __restrict__ conv_w,
                                 const float* __restrict__ conv_b)
{
    int idx = blockIdx.x*blockDim.x + threadIdx.x;   // over MTOT*DI
    if (idx >= MTOT*DI) return;
    int d = idx & (DI-1);
    int m = idx >> 8;
    int t = m & (SEQL-1);
    int b = m >> 12;
    float acc = conv_b[d];
    #pragma unroll
    for (int j=0;j<4;j++){
        int tt = t - 3 + j;
        if (tt >= 0)
            acc = fmaf(conv_w[d*4+j], g_xz[(size_t)((b*SEQL+tt))*512 + d], acc);
    }
    float sv = acc / (1.f + __expf(-acc));   // silu
    g_x[idx] = sv;
}

// ---------------- dt = softplus(dt8 @ dt_proj_w^T + b) ----------------
__global__ void __launch_bounds__(256)
dt_kernel(const float* __restrict__ dtw, const float* __restrict__ dtb)
{
    __shared__ float ws[DI*DRK];
    int tid = threadIdx.x;
    for (int i=tid;i<DI*DRK;i+=256) ws[i]=dtw[i];
    __syncthreads();
    float w[8];
    #pragma unroll
    for (int j=0;j<8;j++) w[j] = ws[tid*8+j];
    float bb = dtb[tid];
    int m0 = blockIdx.x*128;
    for (int r=0;r<128;r++){
        int m = m0 + r;
        const float* xr = &g_xdbl[(size_t)m*40];
        float4 x0 = *reinterpret_cast<const float4*>(xr);
        float4 x1 = *reinterpret_cast<const float4*>(xr+4);
        float acc = bb;
        acc = fmaf(w[0],x0.x, acc); acc = fmaf(w[1],x0.y, acc);
        acc = fmaf(w[2],x0.z, acc); acc = fmaf(w[3],x0.w, acc);
        acc = fmaf(w[4],x1.x, acc); acc = fmaf(w[5],x1.y, acc);
        acc = fmaf(w[6],x1.z, acc); acc = fmaf(w[7],x1.w, acc);
        float sp = (acc > 20.f) ? acc : log1pf(__expf(acc));
        g_dtf[(size_t)m*DI + tid] = sp;
    }
}

// ---------------- scan pass 1: local scan per chunk -> h_end + sum(dt) ----------------
// block: 256 thr = 8 warps; warp covers 8 d (4 lanes/d, 4 states/lane)
__global__ void __launch_bounds__(256)
scan_p1_kernel(const float* __restrict__ A_log)
{
    int c = blockIdx.x, dblk = blockIdx.y, b = blockIdx.z;
    int tid = threadIdx.x;
    int w = tid>>5, l = tid&31, g = l>>2, q = l&3;
    int d = dblk*DPB + w*8 + g;
    int t0 = c*LC;
    size_t m0 = (size_t)b*SEQL + t0;

    __shared__ float Bs[LC][16];
    for (int idx=tid; idx<LC*16; idx+=256){
        int t = idx>>4, s = idx&15;
        Bs[t][s] = g_xdbl[(m0+t)*40 + 8 + s];
    }
    __syncthreads();

    float Aj[4];
    #pragma unroll
    for (int j=0;j<4;j++) Aj[j] = -expf(A_log[d*DS + 4*q + j]);

    float h[4] = {0.f,0.f,0.f,0.f};
    float tsum = 0.f;
    const float* dtp = g_dtf + m0*DI + d;
    const float* up  = g_x   + m0*DI + d;

    #pragma unroll 4
    for (int t=0;t<LC;t++){
        float dtv = __ldg(dtp + (size_t)t*DI);
        float uv  = __ldg(up  + (size_t)t*DI);
        float dtu = dtv*uv;
        float4 Bv = *reinterpret_cast<const float4*>(&Bs[t][4*q]);
        float bb[4] = {Bv.x,Bv.y,Bv.z,Bv.w};
        #pragma unroll
        for (int j=0;j<4;j++){
            float a = __expf(dtv*Aj[j]);
            h[j] = fmaf(a, h[j], dtu*bb[j]);
        }
        tsum += dtv;
    }

    size_t base = ((size_t)(c*BT+b)*DI + d);
    if (q==0) g_tsum[base] = tsum;
    *reinterpret_cast<float4*>(&g_hend[base*DS + 4*q]) =
        make_float4(h[0],h[1],h[2],h[3]);
}

// ---------------- chunk combine: serial over 16 chunks, per state ----------------
__global__ void combine_kernel(const float* __restrict__ A_log)
{
    int idx = blockIdx.x*256 + threadIdx.x;   // 32768 states
    int s = idx & 15;
    int d = (idx>>4) & (DI-1);
    int b = idx >> 12;
    float A = -expf(A_log[d*DS + s]);
    float H = 0.f;
    for (int c=0;c<NCH;c++){
        size_t base = ((size_t)(c*BT+b)*DI + d);
        g_hinit[base*DS + s] = H;
        float P = __expf(A * g_tsum[base]);
        H = fmaf(P, H, g_hend[base*DS + s]);
    }
}

// ---------------- scan pass 2: scan with true init, y + fused gate epilogue ----------------
__global__ void __launch_bounds__(256)
scan_p2_kernel(const float* __restrict__ A_log, const float* __restrict__ Dskip)
{
    int c = blockIdx.x, dblk = blockIdx.y, b = blockIdx.z;
    int tid = threadIdx.x;
    int w = tid>>5, l = tid&31, g = l>>2, q = l&3;
    int d = dblk*DPB + w*8 + g;
    int t0 = c*LC;
    size_t m0 = (size_t)b*SEQL + t0;

    __shared__ float Bs[LC][16];
    __shared__ float Cs[LC][16];
    for (int idx=tid; idx<LC*16; idx+=256){
        int t = idx>>4, s = idx&15;
        const float* row = &g_xdbl[(m0+t)*40 + 8];
        Bs[t][s] = row[s];
        Cs[t][s] = row[16+s];
    }
    __syncthreads();

    float Aj[4];
    #pragma unroll
    for (int j=0;j<4;j++) Aj[j] = -expf(A_log[d*DS + 4*q + j]);

    size_t base = ((size_t)(c*BT+b)*DI + d);
    float4 hv = *reinterpret_cast<const float4*>(&g_hinit[base*DS + 4*q]);
    float h[4] = {hv.x,hv.y,hv.z,hv.w};
    float Dd = Dskip[d];

    const float* dtp = g_dtf + m0*DI + d;
    const float* up  = g_x   + m0*DI + d;
    const float* zp  = g_xz  + m0*512 + 256 + d;
    float* yp        = g_y   + m0*DI + d;

    #pragma unroll 2
    for (int t=0;t<LC;t++){
        float dtv = __ldg(dtp + (size_t)t*DI);
        float uv  = __ldg(up  + (size_t)t*DI);
        float dtu = dtv*uv;
        float4 Bv = *reinterpret_cast<const float4*>(&Bs[t][4*q]);
        float4 Cv = *reinterpret_cast<const float4*>(&Cs[t][4*q]);
        float bb[4] = {Bv.x,Bv.y,Bv.z,Bv.w};
        float cc[4] = {Cv.x,Cv.y,Cv.z,Cv.w};
        float p = 0.f;
        #pragma unroll
        for (int j=0;j<4;j++){
            float a = __expf(dtv*Aj[j]);
            h[j] = fmaf(a, h[j], dtu*bb[j]);
            p = fmaf(h[j], cc[j], p);
        }
        p += __shfl_xor_sync(0xffffffffu, p, 1);
        p += __shfl_xor_sync(0xffffffffu, p, 2);
        if (q==0){
            float yv = fmaf(uv, Dd, p);
            float zv = __ldg(zp + (size_t)t*512);
            float sz = zv / (1.f + __expf(-zv));
            yp[(size_t)t*DI] = yv * sz;
        }
    }
}

// ---------------- layernorm over DM=128 (warp per row) ----------------
__global__ void __launch_bounds__(256)
ln_kernel(const float* __restrict__ gamma, const float* __restrict__ beta)
{
    int row = blockIdx.x*8 + (threadIdx.x>>5);
    int l   = threadIdx.x & 31;
    const float4 v = *reinterpret_cast<const float4*>(&g_h[(size_t)row*DM + l*4]);
    float sum = v.x+v.y+v.z+v.w;
    #pragma unroll
    for (int o=16;o>0;o>>=1) sum += __shfl_xor_sync(0xffffffffu, sum, o);
    float mu = sum * (1.f/128.f);
    float dx=v.x-mu, dy=v.y-mu, dz=v.z-mu, dw=v.w-mu;
    float sq = dx*dx + dy*dy + dz*dz + dw*dw;
    #pragma unroll
    for (int o=16;o>0;o>>=1) sq += __shfl_xor_sync(0xffffffffu, sq, o);
    float rs = rsqrtf(sq*(1.f/128.f) + 1e-5f);
    const float4 gv = *reinterpret_cast<const float4*>(&gamma[l*4]);
    const float4 bv = *reinterpret_cast<const float4*>(&beta[l*4]);
    float4 o4;
    o4.x = fmaf(dx*rs, gv.x, bv.x);
    o4.y = fmaf(dy*rs, gv.y, bv.y);
    o4.z = fmaf(dz*rs, gv.z, bv.z);
    o4.w = fmaf(dw*rs, gv.w, bv.w);
    *reinterpret_cast<float4*>(&g_hn[(size_t)row*DM + l*4]) = o4;
}

// ---------------- launch ----------------
extern "C" void kernel_launch(void* const* d_in, const int* in_sizes, int n_in,
                              void* d_out, int out_size)
{
    const float* s_in       = (const float*)d_in[0];
    const float* in_proj_w  = (const float*)d_in[1];
    const float* conv_w     = (const float*)d_in[2];
    const float* conv_b     = (const float*)d_in[3];
    const float* x_proj_w   = (const float*)d_in[4];
    const float* dt_proj_w  = (const float*)d_in[5];
    const float* dt_proj_b  = (const float*)d_in[6];
    const float* A_log      = (const float*)d_in[7];
    const float* D_skip     = (const float*)d_in[8];
    const float* out_proj_w = (const float*)d_in[9];
    const float* ln_gamma   = (const float*)d_in[10];
    const float* ln_beta    = (const float*)d_in[11];
    const float* fc_w       = (const float*)d_in[12];
    float* out = (float*)d_out;

    float *xz, *x, *xdbl, *y, *h, *hn;
    cudaGetSymbolAddress((void**)&xz,   g_xz);
    cudaGetSymbolAddress((void**)&x,    g_x);
    cudaGetSymbolAddress((void**)&xdbl, g_xdbl);
    cudaGetSymbolAddress((void**)&y,    g_y);
    cudaGetSymbolAddress((void**)&h,    g_h);
    cudaGetSymbolAddress((void**)&hn,   g_hn);

    // 1. xz = s @ in_proj_w^T   [32768,128] x [512,128]^T
    sgemm_nt<128,128,32,8,8,0><<<dim3(512/128, MTOT/128), 256>>>(
        s_in, in_proj_w, xz, MTOT, 512, DM);

    // 2. depthwise conv + silu -> g_x
    conv_silu_kernel<<<(MTOT*DI)/256, 256>>>(conv_w, conv_b);

    // 3. x_dbl = x @ x_proj_w^T  [32768,256] x [40,256]^T
    sgemm_nt<128,64,32,8,4,0><<<dim3(1, MTOT/128), 256>>>(
        x, x_proj_w, xdbl, MTOT, 40, DI);

    // 4. dt = softplus(dt8 @ dt_proj_w^T + b)
    dt_kernel<<<MTOT/128, 256>>>(dt_proj_w, dt_proj_b);

    // 5. chunked selective scan
    scan_p1_kernel<<<dim3(NCH, DI/DPB, BT), 256>>>(A_log);
    combine_kernel<<<(BT*DI*DS)/256, 256>>>(A_log);
    scan_p2_kernel<<<dim3(NCH, DI/DPB, BT), 256>>>(A_log, D_skip);

    // 6. h = y @ out_proj_w^T  [32768,256] x [128,256]^T
    sgemm_nt<64,128,32,4,8,0><<<dim3(1, MTOT/64), 256>>>(
        y, out_proj_w, h, MTOT, DM, DI);

    // 7. layernorm
    ln_kernel<<<MTOT/8, 256>>>(ln_gamma, ln_beta);

    // 8. out = relu(hn @ fc_w^T)  [32768,128] x [128,128]^T
    sgemm_nt<64,128,32,4,8,1><<<dim3(1, MTOT/64), 256>>>(
        hn, fc_w, out, MTOT, DM, DM);
}

// round 2
// speedup vs baseline: 1.5328x; 1.5328x over previous
#include <cuda_runtime.h>
#include <cstdint>
#include <cstddef>

// ---------------- problem constants ----------------
#define BT   8
#define SEQL 4096
#define DM   128
#define DI   256
#define DS   16
#define DRK  8
#define MTOT (BT*SEQL)          // 32768 rows
#define NCH  16                 // scan chunks
#define LC   (SEQL/NCH)         // 256 steps per chunk
#define DPB  64                 // d-channels per scan block

// ---------------- scratch (device globals; no allocs) ----------------
__device__ float g_xz  [(size_t)MTOT*512];  // in_proj output: x raw [0:256), z [256:512)
__device__ float g_x   [(size_t)MTOT*DI];   // conv+silu output (u)
__device__ float g_xdbl[(size_t)MTOT*40];   // x_proj output: dt8[0:8) B[8:24) C[24:40)
__device__ float g_dtf [(size_t)MTOT*DI];   // softplus(dt_proj)
__device__ float g_y   [(size_t)MTOT*DI];   // scan output, fused gate
__device__ float g_h   [(size_t)MTOT*DM];   // out_proj output
__device__ float g_hn  [(size_t)MTOT*DM];   // layernorm output
__device__ float g_hend [NCH*BT*DI*DS];
__device__ float g_hinit[NCH*BT*DI*DS];
__device__ float g_tsum [NCH*BT*DI];

// ---------------- tf32 helpers ----------------
__device__ __forceinline__ uint32_t f2tf32(float f){
    uint32_t r;
    asm("cvt.rna.tf32.f32 %0, %1;" : "=r"(r) : "f"(f));
    return r;
}

// ---------------- tensor-core GEMM: C[M,N] = A[M,K] * B[N,K]^T, tf32 ----------------
// A row-major [M,K], B row-major [N,K] (weight layout). ACT: 0=none, 1=relu.
// Shared layout uses k-interleave within each k8 group: col = g*8 + 2*(k&3) + (k>>2),
// so each mma fragment is a single conflict-free LDS.64.
template<int BM,int BN,int BK,int WM,int WN,int ACT>
__global__ void __launch_bounds__((BM/WM)*(BN/WN)*32)
mma_tf32_nt(const float* __restrict__ A, const float* __restrict__ B,
            float* __restrict__ C, int M, int N, int K)
{
    constexpr int WARPS_N = BN/WN;
    constexpr int NTHR = (BM/WM)*(BN/WN)*32;
    constexpr int MT = WM/16;
    constexpr int NT = WN/8;
    constexpr int LDSW = BK + 8;   // 40 words: conflict-free frag loads

    __shared__ uint32_t As[BM][LDSW];
    __shared__ uint32_t Bs[BN][LDSW];

    const int tid  = threadIdx.x;
    const int wid  = tid >> 5;
    const int lane = tid & 31;
    const int wm   = wid / WARPS_N;
    const int wn   = wid % WARPS_N;
    const int m0   = blockIdx.y * BM;
    const int n0   = blockIdx.x * BN;
    const int tig  = lane & 3;
    const int grp  = lane >> 2;

    float acc[MT][NT][4];
    #pragma unroll
    for (int i=0;i<MT;i++)
        #pragma unroll
        for (int j=0;j<NT;j++){
            acc[i][j][0]=0.f; acc[i][j][1]=0.f;
            acc[i][j][2]=0.f; acc[i][j][3]=0.f;
        }

    for (int k0=0; k0<K; k0+=BK){
        // ---- stage A tile ----
        #pragma unroll
        for (int it=0; it<(BM*BK/4)/NTHR; ++it){
            int idx = tid + it*NTHR;
            int m = idx >> 3, q = idx & 7;   // q: which k-quad [0,8)
            float4 v = *reinterpret_cast<const float4*>(
                &A[(size_t)(m0+m)*K + k0 + q*4]);
            int g = q>>1, o = q&1;
            As[m][g*8 + 0 + o] = f2tf32(v.x);
            As[m][g*8 + 2 + o] = f2tf32(v.y);
            As[m][g*8 + 4 + o] = f2tf32(v.z);
            As[m][g*8 + 6 + o] = f2tf32(v.w);
        }
        // ---- stage B tile (guard n >= N) ----
        #pragma unroll
        for (int it=0; it<(BN*BK/4)/NTHR; ++it){
            int idx = tid + it*NTHR;
            int n = idx >> 3, q = idx & 7;
            float4 v = make_float4(0.f,0.f,0.f,0.f);
            if (n0+n < N)
                v = *reinterpret_cast<const float4*>(
                    &B[(size_t)(n0+n)*K + k0 + q*4]);
            int g = q>>1, o = q&1;
            Bs[n][g*8 + 0 + o] = f2tf32(v.x);
            Bs[n][g*8 + 2 + o] = f2tf32(v.y);
            Bs[n][g*8 + 4 + o] = f2tf32(v.z);
            Bs[n][g*8 + 6 + o] = f2tf32(v.w);
        }
        __syncthreads();

        #pragma unroll
        for (int ks=0; ks<BK/8; ks++){
            uint32_t af[MT][4], bf[NT][2];
            #pragma unroll
            for (int mt=0; mt<MT; mt++){
                int row = wm*WM + mt*16 + grp;
                uint2 lo = *reinterpret_cast<const uint2*>(&As[row  ][ks*8 + 2*tig]);
                uint2 hi = *reinterpret_cast<const uint2*>(&As[row+8][ks*8 + 2*tig]);
                af[mt][0]=lo.x; af[mt][2]=lo.y;   // (row,  k=c) (row,  k=c+4)
                af[mt][1]=hi.x; af[mt][3]=hi.y;   // (row+8,k=c) (row+8,k=c+4)
            }
            #pragma unroll
            for (int nt=0; nt<NT; nt++){
                int n = wn*WN + nt*8 + grp;
                uint2 b = *reinterpret_cast<const uint2*>(&Bs[n][ks*8 + 2*tig]);
                bf[nt][0]=b.x; bf[nt][1]=b.y;
            }
            #pragma unroll
            for (int mt=0; mt<MT; mt++)
                #pragma unroll
                for (int nt=0; nt<NT; nt++){
                    asm volatile(
                        "mma.sync.aligned.m16n8k8.row.col.f32.tf32.tf32.f32 "
                        "{%0,%1,%2,%3}, {%4,%5,%6,%7}, {%8,%9}, {%0,%1,%2,%3};"
                        : "+f"(acc[mt][nt][0]), "+f"(acc[mt][nt][1]),
                          "+f"(acc[mt][nt][2]), "+f"(acc[mt][nt][3])
                        : "r"(af[mt][0]), "r"(af[mt][1]),
                          "r"(af[mt][2]), "r"(af[mt][3]),
                          "r"(bf[nt][0]), "r"(bf[nt][1]));
                }
        }
        __syncthreads();
    }

    // ---- epilogue ----
    #pragma unroll
    for (int mt=0; mt<MT; mt++){
        int row = m0 + wm*WM + mt*16 + grp;
        #pragma unroll
        for (int nt=0; nt<NT; nt++){
            int col = n0 + wn*WN + nt*8 + 2*tig;
            if (col < N){
                float2 v0 = make_float2(acc[mt][nt][0], acc[mt][nt][1]);
                float2 v1 = make_float2(acc[mt][nt][2], acc[mt][nt][3]);
                if (ACT==1){
                    v0.x=fmaxf(v0.x,0.f); v0.y=fmaxf(v0.y,0.f);
                    v1.x=fmaxf(v1.x,0.f); v1.y=fmaxf(v1.y,0.f);
                }
                *reinterpret_cast<float2*>(&C[(size_t)row*N + col])     = v0;
                *reinterpret_cast<float2*>(&C[(size_t)(row+8)*N + col]) = v1;
            }
        }
    }
}

// ---------------- depthwise causal conv (k=4) + bias + silu ----------------
__global__ void conv_silu_kernel(const float* __restrict__ conv_w,
                                 const float* __restrict__ conv_b)
{
    int idx = blockIdx.x*blockDim.x + threadIdx.x;   // over MTOT*DI
    if (idx >= MTOT*DI) return;
    int d = idx & (DI-1);
    int m = idx >> 8;
    int t = m & (SEQL-1);
    int b = m >> 12;
    float acc = conv_b[d];
    #pragma unroll
    for (int j=0;j<4;j++){
        int tt = t - 3 + j;
        if (tt >= 0)
            acc = fmaf(conv_w[d*4+j], g_xz[(size_t)((b*SEQL+tt))*512 + d], acc);
    }
    float sv = acc / (1.f + __expf(-acc));   // silu
    g_x[idx] = sv;
}

// ---------------- dt = softplus(dt8 @ dt_proj_w^T + b) (parallel, staged) ----------------
__global__ void __launch_bounds__(256)
dt_kernel(const float* __restrict__ dtw, const float* __restrict__ dtb)
{
    __shared__ float ws[DI*DRK];
    __shared__ float xs[64][9];     // 64 rows x 8 (+pad)
    int tid = threadIdx.x;
    for (int i=tid;i<DI*DRK;i+=256) ws[i]=dtw[i];
    size_t m0 = (size_t)blockIdx.x * 64;
    for (int i=tid;i<64*8;i+=256){
        int r = i>>3, c = i&7;
        xs[r][c] = g_xdbl[(m0+r)*40 + c];
    }
    __syncthreads();

    float w[8];
    #pragma unroll
    for (int j=0;j<8;j++) w[j] = ws[tid*8+j];
    float bb = dtb[tid];

    #pragma unroll 4
    for (int r=0;r<64;r++){
        float acc = bb;
        #pragma unroll
        for (int j=0;j<8;j++) acc = fmaf(w[j], xs[r][j], acc);
        float sp = (acc > 20.f) ? acc : log1pf(__expf(acc));
        g_dtf[(m0+r)*DI + tid] = sp;
    }
}

// ---------------- scan pass 1: local scan per chunk -> h_end + sum(dt) ----------------
__global__ void __launch_bounds__(256)
scan_p1_kernel(const float* __restrict__ A_log)
{
    int c = blockIdx.x, dblk = blockIdx.y, b = blockIdx.z;
    int tid = threadIdx.x;
    int w = tid>>5, l = tid&31, g = l>>2, q = l&3;
    int d = dblk*DPB + w*8 + g;
    int t0 = c*LC;
    size_t m0 = (size_t)b*SEQL + t0;

    __shared__ float Bs[LC][16];
    for (int idx=tid; idx<LC*16; idx+=256){
        int t = idx>>4, s = idx&15;
        Bs[t][s] = g_xdbl[(m0+t)*40 + 8 + s];
    }
    __syncthreads();

    float Aj[4];
    #pragma unroll
    for (int j=0;j<4;j++) Aj[j] = -expf(A_log[d*DS + 4*q + j]);

    float h[4] = {0.f,0.f,0.f,0.f};
    float tsum = 0.f;
    const float* dtp = g_dtf + m0*DI + d;
    const float* up  = g_x   + m0*DI + d;

    #pragma unroll 4
    for (int t=0;t<LC;t++){
        float dtv = __ldg(dtp + (size_t)t*DI);
        float uv  = __ldg(up  + (size_t)t*DI);
        float dtu = dtv*uv;
        float4 Bv = *reinterpret_cast<const float4*>(&Bs[t][4*q]);
        float bb[4] = {Bv.x,Bv.y,Bv.z,Bv.w};
        #pragma unroll
        for (int j=0;j<4;j++){
            float a = __expf(dtv*Aj[j]);
            h[j] = fmaf(a, h[j], dtu*bb[j]);
        }
        tsum += dtv;
    }

    size_t base = ((size_t)(c*BT+b)*DI + d);
    if (q==0) g_tsum[base] = tsum;
    *reinterpret_cast<float4*>(&g_hend[base*DS + 4*q]) =
        make_float4(h[0],h[1],h[2],h[3]);
}

// ---------------- chunk combine: serial over 16 chunks, per state ----------------
__global__ void combine_kernel(const float* __restrict__ A_log)
{
    int idx = blockIdx.x*256 + threadIdx.x;   // 32768 states
    int s = idx & 15;
    int d = (idx>>4) & (DI-1);
    int b = idx >> 12;
    float A = -expf(A_log[d*DS + s]);
    float H = 0.f;
    for (int c=0;c<NCH;c++){
        size_t base = ((size_t)(c*BT+b)*DI + d);
        g_hinit[base*DS + s] = H;
        float P = __expf(A * g_tsum[base]);
        H = fmaf(P, H, g_hend[base*DS + s]);
    }
}

// ---------------- scan pass 2: scan with true init, y + fused gate epilogue ----------------
__global__ void __launch_bounds__(256)
scan_p2_kernel(const float* __restrict__ A_log, const float* __restrict__ Dskip)
{
    int c = blockIdx.x, dblk = blockIdx.y, b = blockIdx.z;
    int tid = threadIdx.x;
    int w = tid>>5, l = tid&31, g = l>>2, q = l&3;
    int d = dblk*DPB + w*8 + g;
    int t0 = c*LC;
    size_t m0 = (size_t)b*SEQL + t0;

    __shared__ float Bs[LC][16];
    __shared__ float Cs[LC][16];
    for (int idx=tid; idx<LC*16; idx+=256){
        int t = idx>>4, s = idx&15;
        const float* row = &g_xdbl[(m0+t)*40 + 8];
        Bs[t][s] = row[s];
        Cs[t][s] = row[16+s];
    }
    __syncthreads();

    float Aj[4];
    #pragma unroll
    for (int j=0;j<4;j++) Aj[j] = -expf(A_log[d*DS + 4*q + j]);

    size_t base = ((size_t)(c*BT+b)*DI + d);
    float4 hv = *reinterpret_cast<const float4*>(&g_hinit[base*DS + 4*q]);
    float h[4] = {hv.x,hv.y,hv.z,hv.w};
    float Dd = Dskip[d];

    const float* dtp = g_dtf + m0*DI + d;
    const float* up  = g_x   + m0*DI + d;
    const float* zp  = g_xz  + m0*512 + 256 + d;
    float* yp        = g_y   + m0*DI + d;

    #pragma unroll 2
    for (int t=0;t<LC;t++){
        float dtv = __ldg(dtp + (size_t)t*DI);
        float uv  = __ldg(up  + (size_t)t*DI);
        float dtu = dtv*uv;
        float4 Bv = *reinterpret_cast<const float4*>(&Bs[t][4*q]);
        float4 Cv = *reinterpret_cast<const float4*>(&Cs[t][4*q]);
        float bb[4] = {Bv.x,Bv.y,Bv.z,Bv.w};
        float cc[4] = {Cv.x,Cv.y,Cv.z,Cv.w};
        float p = 0.f;
        #pragma unroll
        for (int j=0;j<4;j++){
            float a = __expf(dtv*Aj[j]);
            h[j] = fmaf(a, h[j], dtu*bb[j]);
            p = fmaf(h[j], cc[j], p);
        }
        p += __shfl_xor_sync(0xffffffffu, p, 1);
        p += __shfl_xor_sync(0xffffffffu, p, 2);
        if (q==0){
            float yv = fmaf(uv, Dd, p);
            float zv = __ldg(zp + (size_t)t*512);
            float sz = zv / (1.f + __expf(-zv));
            yp[(size_t)t*DI] = yv * sz;
        }
    }
}

// ---------------- layernorm over DM=128 (warp per row) ----------------
__global__ void __launch_bounds__(256)
ln_kernel(const float* __restrict__ gamma, const float* __restrict__ beta)
{
    int row = blockIdx.x*8 + (threadIdx.x>>5);
    int l   = threadIdx.x & 31;
    const float4 v = *reinterpret_cast<const float4*>(&g_h[(size_t)row*DM + l*4]);
    float sum = v.x+v.y+v.z+v.w;
    #pragma unroll
    for (int o=16;o>0;o>>=1) sum += __shfl_xor_sync(0xffffffffu, sum, o);
    float mu = sum * (1.f/128.f);
    float dx=v.x-mu, dy=v.y-mu, dz=v.z-mu, dw=v.w-mu;
    float sq = dx*dx + dy*dy + dz*dz + dw*dw;
    #pragma unroll
    for (int o=16;o>0;o>>=1) sq += __shfl_xor_sync(0xffffffffu, sq, o);
    float rs = rsqrtf(sq*(1.f/128.f) + 1e-5f);
    const float4 gv = *reinterpret_cast<const float4*>(&gamma[l*4]);
    const float4 bv = *reinterpret_cast<const float4*>(&beta[l*4]);
    float4 o4;
    o4.x = fmaf(dx*rs, gv.x, bv.x);
    o4.y = fmaf(dy*rs, gv.y, bv.y);
    o4.z = fmaf(dz*rs, gv.z, bv.z);
    o4.w = fmaf(dw*rs, gv.w, bv.w);
    *reinterpret_cast<float4*>(&g_hn[(size_t)row*DM + l*4]) = o4;
}

// ---------------- launch ----------------
extern "C" void kernel_launch(void* const* d_in, const int* in_sizes, int n_in,
                              void* d_out, int out_size)
{
    const float* s_in       = (const float*)d_in[0];
    const float* in_proj_w  = (const float*)d_in[1];
    const float* conv_w     = (const float*)d_in[2];
    const float* conv_b     = (const float*)d_in[3];
    const float* x_proj_w   = (const float*)d_in[4];
    const float* dt_proj_w  = (const float*)d_in[5];
    const float* dt_proj_b  = (const float*)d_in[6];
    const float* A_log      = (const float*)d_in[7];
    const float* D_skip     = (const float*)d_in[8];
    const float* out_proj_w = (const float*)d_in[9];
    const float* ln_gamma   = (const float*)d_in[10];
    const float* ln_beta    = (const float*)d_in[11];
    const float* fc_w       = (const float*)d_in[12];
    float* out = (float*)d_out;

    float *xz, *x, *xdbl, *y, *h, *hn;
    cudaGetSymbolAddress((void**)&xz,   g_xz);
    cudaGetSymbolAddress((void**)&x,    g_x);
    cudaGetSymbolAddress((void**)&xdbl, g_xdbl);
    cudaGetSymbolAddress((void**)&y,    g_y);
    cudaGetSymbolAddress((void**)&h,    g_h);
    cudaGetSymbolAddress((void**)&hn,   g_hn);

    // 1. xz = s @ in_proj_w^T   [32768,128] x [512,128]^T
    mma_tf32_nt<128,128,32,64,32,0><<<dim3(512/128, MTOT/128), 256>>>(
        s_in, in_proj_w, xz, MTOT, 512, DM);

    // 2. depthwise conv + silu -> g_x
    conv_silu_kernel<<<(MTOT*DI)/256, 256>>>(conv_w, conv_b);

    // 3. x_dbl = x @ x_proj_w^T  [32768,256] x [40,256]^T
    mma_tf32_nt<128,64,32,64,32,0><<<dim3(1, MTOT/128), 128>>>(
        x, x_proj_w, xdbl, MTOT, 40, DI);

    // 4. dt = softplus(dt8 @ dt_proj_w^T + b)
    dt_kernel<<<MTOT/64, 256>>>(dt_proj_w, dt_proj_b);

    // 5. chunked selective scan
    scan_p1_kernel<<<dim3(NCH, DI/DPB, BT), 256>>>(A_log);
    combine_kernel<<<(BT*DI*DS)/256, 256>>>(A_log);
    scan_p2_kernel<<<dim3(NCH, DI/DPB, BT), 256>>>(A_log, D_skip);

    // 6. h = y @ out_proj_w^T  [32768,256] x [128,256]^T
    mma_tf32_nt<128,128,32,64,32,0><<<dim3(1, MTOT/128), 256>>>(
        y, out_proj_w, h, MTOT, DM, DI);

    // 7. layernorm
    ln_kernel<<<MTOT/8, 256>>>(ln_gamma, ln_beta);

    // 8. out = relu(hn @ fc_w^T)  [32768,128] x [128,128]^T
    mma_tf32_nt<128,128,32,64,32,1><<<dim3(1, MTOT/128), 256>>>(
        hn, fc_w, out, MTOT, DM, DM);
}